// round 15
// baseline (speedup 1.0000x reference)
#include <cuda_runtime.h>
#include <cuda_bf16.h>
#include <cuda_fp16.h>
#include <stdint.h>

#define BATCH 4
#define CC    256
#define HH    192
#define WWID  192
#define HW    (HH*WWID)
#define NH    16
#define DH    16
#define WS    8
#define PB2   576          // 64-pixel tiles per batch image
#define PT2   (PB2*BATCH)  // 2304 total p-tiles

// ---------------- scratch (static device globals; no allocation) ----------------
// plain fp16 activations, [b][p][c] channel-contiguous
__device__ __align__(16) __half g_xt2[(size_t)BATCH * HW * CC];
__device__ __align__(16) __half g_dwt2[(size_t)BATCH * HW * CC];
__device__ __align__(16) float g_qkvw[(size_t)3 * BATCH * NH * 576 * DH * 64]; // window layout
__device__ float g_local[(size_t)BATCH * CC * HW];
__device__ float g_attn[(size_t)BATCH * CC * HW];
__device__ float g_st[(size_t)BATCH * CC * HW];
__device__ float g_wl[CC * CC * 9];
__device__ float g_bl[CC];
__device__ float g_wpw[CC * CC];
__device__ float g_bpw[CC];
__device__ __align__(16) __half g_wqA[768 * CC];      // [oc][k] fp16
__device__ __align__(16) __half g_wlA[CC * 9 * CC];   // [oc][t*256+ic] fp16
__device__ __align__(16) __half g_wpA[CC * CC];       // [oc][k] fp16

// ---------------- PTX helpers (baseline sm_80+/sm_100 features only) ----------------
__device__ __forceinline__ uint32_t s2u(const void* p) {
    uint32_t a;
    asm("{ .reg .u64 t; cvta.to.shared.u64 t, %1; cvt.u32.u64 %0, t; }" : "=r"(a) : "l"(p));
    return a;
}
__device__ __forceinline__ void cp16(uint32_t s, const void* g) {
    asm volatile("cp.async.cg.shared.global [%0], [%1], 16;" :: "r"(s), "l"(g));
}
__device__ __forceinline__ void cp16z(uint32_t s, const void* g, int sz) {
    asm volatile("cp.async.cg.shared.global [%0], [%1], 16, %2;" :: "r"(s), "l"(g), "r"(sz));
}
#define CP_COMMIT() asm volatile("cp.async.commit_group;" ::: "memory")
#define CP_WAIT(N)  asm volatile("cp.async.wait_group %0;" :: "n"(N) : "memory")

#define LDSM4(r, addr) \
    asm volatile("ldmatrix.sync.aligned.m8n8.x4.shared.b16 {%0,%1,%2,%3}, [%4];" \
        : "=r"((r)[0]), "=r"((r)[1]), "=r"((r)[2]), "=r"((r)[3]) : "r"(addr))

// fp16 inputs, fp32 accumulate
#define MMA16816(d, a, b0v, b1v) \
    asm volatile("mma.sync.aligned.m16n8k16.row.col.f32.f16.f16.f32 " \
        "{%0,%1,%2,%3},{%4,%5,%6,%7},{%8,%9},{%0,%1,%2,%3};" \
        : "+f"((d)[0]), "+f"((d)[1]), "+f"((d)[2]), "+f"((d)[3]) \
        : "r"((a)[0]), "r"((a)[1]), "r"((a)[2]), "r"((a)[3]), "r"(b0v), "r"(b1v))

// packed dual-fp32 FMA (Blackwell): d = a*b + d
__device__ __forceinline__ void fma2(float2& d, const float2& a, const float2& b) {
    asm("fma.rn.f32x2 %0, %1, %2, %0;"
        : "+l"(reinterpret_cast<unsigned long long&>(d))
        : "l"(reinterpret_cast<const unsigned long long&>(a)),
          "l"(reinterpret_cast<const unsigned long long&>(b)));
}
__device__ __forceinline__ void add2(float2& d, const float2& a) {
    asm("add.rn.f32x2 %0, %1, %0;"
        : "+l"(reinterpret_cast<unsigned long long&>(d))
        : "l"(reinterpret_cast<const unsigned long long&>(a)));
}

__device__ __host__ __forceinline__ size_t qidx(int sel, int b, int hd, int win) {
    return ((size_t)((sel * 4 + b) * 16 + hd) * 576 + win) * 1024;
}

// ---------------- weight fusion (fp32) ----------------
__global__ void fuse_weights(const float* __restrict__ w_local1,
                             const float* __restrict__ bn1_s, const float* __restrict__ bn1_b,
                             const float* __restrict__ w_local2,
                             const float* __restrict__ bn2_s, const float* __restrict__ bn2_b,
                             const float* __restrict__ w_pw,
                             const float* __restrict__ bnp_s, const float* __restrict__ bnp_b) {
    int i = blockIdx.x * blockDim.x + threadIdx.x;
    const int N1 = CC * CC * 9;
    if (i < N1) {
        int oc = i / (CC * 9);
        int r = i - oc * (CC * 9);
        int ic = r / 9;
        int t = r - ic * 9;
        float v = bn1_s[oc] * w_local1[i];
        if (t == 4) v += bn2_s[oc] * w_local2[oc * CC + ic];
        g_wl[i] = v;
    }
    if (i < CC * CC) {
        int ic = i & (CC - 1);
        g_wpw[i] = w_pw[i] * bnp_s[ic];
    }
    if (i < CC) {
        g_bl[i] = bn1_b[i] + bn2_b[i];
        float s = 0.f;
        for (int ic = 0; ic < CC; ic++) s += w_pw[i * CC + ic] * bnp_b[ic];
        g_bpw[i] = s;
    }
}

// ---------------- weight fp16 packing ----------------
__global__ void prep_pack(const float* __restrict__ w_qkv) {
    int i = blockIdx.x * blockDim.x + threadIdx.x;
    if (i < 768 * 256) g_wqA[i] = __float2half_rn(w_qkv[i]);
    if (i < 256 * 256) g_wpA[i] = __float2half_rn(g_wpw[i]);
    if (i < 256 * 2304) {   // k = t*256+ic maps from g_wl[oc][ic*9+t]
        int oc = i / 2304;
        int k = i - oc * 2304;
        int t = k >> 8, ic = k & 255;
        g_wlA[i] = __float2half_rn(g_wl[oc * 2304 + ic * 9 + t]);
    }
}

// ---------------- transpose + convert: x [b][c][p] fp32 -> [b][p][c] fp16 ----------------
__global__ void tconv_kernel(const float* __restrict__ xin) {
    __shared__ float t[32][33];
    int b = blockIdx.z, c0 = blockIdx.y * 32, p0 = blockIdx.x * 32;
    int tx = threadIdx.x, ty = threadIdx.y;
#pragma unroll
    for (int i = 0; i < 4; i++)
        t[ty + i * 8][tx] = xin[((size_t)(b * CC + c0 + ty + i * 8)) * HW + p0 + tx];
    __syncthreads();
#pragma unroll
    for (int i = 0; i < 4; i++) {
        int p = p0 + ty + i * 8;
        g_xt2[((size_t)b * HW + p) * CC + c0 + tx] = __float2half_rn(t[tx][ty + i * 8]);
    }
}

// ---------------- mma.sync plain-fp16 GEMM, 128x64 tile, 3 CTAs/SM ----------------
// D[oc][p] = sum_k W[oc][k] * X[p][k]
// grid = (oc_tiles, pixel_tiles); pixel tile = 64 px. 3-stage ring, 24KB/stage.
// OP: 0 = qkv (OC=768) -> window layout g_qkvw
//     1 = conv3x3 implicit (OC=256, K=2304 t-outer) -> g_local
//     2 = pointwise (OC=256) -> outp
template<int OP>
__global__ void __launch_bounds__(256, 3) gemm_kernel(float* __restrict__ outp) {
    extern __shared__ char smem[];
    const int NCH = (OP == 1) ? 36 : 4;   // chunks of 64 real k
    const int OCT = (OP == 0) ? 768 : 256;
    const uint4* A = (OP == 0) ? (const uint4*)g_wqA : (OP == 1) ? (const uint4*)g_wlA : (const uint4*)g_wpA;
    const uint4* X = (OP == 2) ? (const uint4*)g_dwt2 : (const uint4*)g_xt2;
    const float* bias = (OP == 1) ? g_bl : (OP == 2) ? g_bpw : nullptr;
    float* out = (OP == 1) ? g_local : outp;
    const int AR = NCH * 8;               // uint4 per A row
    const int XR = 32;                    // uint4 per X pixel row (256 fp16)
    const int STG = 24576;                // stage stride: A 16KB + B 8KB
    const int RING = 3 * STG;

    uint32_t sb = s2u(smem);
    int tid = threadIdx.x;
    int ti = blockIdx.y;                  // pixel tile (slow)
    int b = ti / PB2;
    int pl0 = (ti - (ti / PB2) * PB2) * 64;
    int oc0 = blockIdx.x * 128;           // oc tile (fast) -> wave shares B in L2

    // ---- per-thread loader constants ----
    int r0 = tid >> 3, c16 = tid & 7;     // r0: 0..31
    uint32_t swz = (uint32_t)((c16 ^ (r0 & 7)) << 4);
    uint32_t sArel = (uint32_t)(r0 * 128) + swz;            // + i*4096
    const uint4* aCur = A + (size_t)(oc0 + r0) * AR + c16;  // += 8 per chunk
    const uint4* xCur;                                       // OP!=1
    const uint4* xPtr[2];                                    // OP==1 (2 B rows/thread)
    int hI[2], wI[2];
    if (OP != 1) {
        xCur = X + ((size_t)b * HW + pl0 + r0) * XR + c16;
    } else {
#pragma unroll
        for (int i = 0; i < 2; i++) {
            int pl = pl0 + r0 + 32 * i;
            hI[i] = pl / 192; wI[i] = pl - hI[i] * 192;
            xPtr[i] = X + ((size_t)b * HW + pl) * XR + c16;
        }
    }

    auto load_chunk = [&](int c, uint32_t Ab) {
#pragma unroll
        for (int i = 0; i < 4; i++)       // A: 128 rows
            cp16(Ab + sArel + i * 4096, aCur + (size_t)i * 32 * AR);
        aCur += 8;
        if (OP != 1) {
#pragma unroll
            for (int i = 0; i < 2; i++)   // B: 64 rows
                cp16(Ab + 16384 + sArel + i * 4096, xCur + i * 32 * XR);
            xCur += 8;
        } else {
            int t = c >> 2, cc = c & 3;
            int ky = t / 3 - 1, kx = t - (t / 3) * 3 - 1;
            int off = (ky * 192 + kx) * XR + cc * 8;
#pragma unroll
            for (int i = 0; i < 2; i++) {
                bool ok = ((unsigned)(hI[i] + ky) < 192u) && ((unsigned)(wI[i] + kx) < 192u);
                cp16z(Ab + 16384 + sArel + i * 4096, ok ? (xPtr[i] + off) : X, ok ? 16 : 0);
            }
        }
        CP_COMMIT();
    };

    float acc[4][2][4];
#pragma unroll
    for (int mf = 0; mf < 4; mf++)
#pragma unroll
        for (int nf = 0; nf < 2; nf++)
#pragma unroll
            for (int e = 0; e < 4; e++) acc[mf][nf][e] = 0.f;

    int lane = tid & 31, w = tid >> 5, wm = w & 1, wn = w >> 1;   // 2m x 4n
    int la = lane & 15, ls = lane >> 4;
    int sAsw = la & 7;
    int brow_i = wn * 16 + (lane & 7) + ((lane >> 3) & 1) * 8;
    int sBsw = lane & 7;
    uint32_t arowRel = (uint32_t)((wm * 64 + la) * 128);
    uint32_t browRel = 16384u + (uint32_t)(brow_i * 128);
    uint32_t achK[4], bchK[4];
#pragma unroll
    for (int kp = 0; kp < 4; kp++) {
        achK[kp] = (uint32_t)(((2 * kp + ls) ^ sAsw) << 4);
        bchK[kp] = (uint32_t)(((2 * kp + ls) ^ sBsw) << 4);
    }

    load_chunk(0, sb);
    load_chunk(1, sb + STG);
    uint32_t AbC = sb;                 // compute buffer
    uint32_t AbL = sb + 2 * STG;       // next load buffer
    for (int c = 0; c < NCH; c++) {
        if (c == NCH - 1) { CP_WAIT(0); } else { CP_WAIT(1); }
        __syncthreads();
        if (c + 2 < NCH) {
            load_chunk(c + 2, AbL);
            AbL += STG; if (AbL == sb + RING) AbL = sb;
        }
        uint32_t arow = AbC + arowRel;
        uint32_t brow = AbC + browRel;
        AbC += STG; if (AbC == sb + RING) AbC = sb;
#pragma unroll
        for (int kp = 0; kp < 4; kp++) {
            uint32_t brh[4];
            LDSM4(brh, brow + bchK[kp]);
#pragma unroll
            for (int mf = 0; mf < 4; mf++) {
                uint32_t ah[4];
                LDSM4(ah, arow + mf * 2048 + achK[kp]);
#pragma unroll
                for (int nf = 0; nf < 2; nf++)
                    MMA16816(acc[mf][nf], ah, brh[nf], brh[nf + 2]);
            }
        }
    }

    // epilogue
    int gid = lane >> 2, tig = lane & 3;
    if (OP == 0) {
        // scatter into window layout [sel][b][hd][win][d][token]
#pragma unroll
        for (int mf = 0; mf < 4; mf++) {
#pragma unroll
            for (int r = 0; r < 2; r++) {
                int ocr = oc0 + wm * 64 + mf * 16 + gid + r * 8;
                int sel = ocr >> 8, hd = (ocr >> 4) & 15, d = ocr & 15;
                float* bp = g_qkvw + qidx(sel, b, hd, 0) + d * 64;
#pragma unroll
                for (int nf = 0; nf < 2; nf++) {
                    int pixel = pl0 + wn * 16 + 2 * tig + nf * 8;
                    int py = pixel / 192, px = pixel - py * 192;
                    int win = (py >> 3) * 24 + (px >> 3);
                    int token = ((py & 7) << 3) + (px & 7);
                    float2 v = {acc[mf][nf][2 * r], acc[mf][nf][2 * r + 1]};
                    *(float2*)(bp + (size_t)win * 1024 + token) = v;
                }
            }
        }
    } else {
#pragma unroll
        for (int mf = 0; mf < 4; mf++) {
            int oc = oc0 + wm * 64 + mf * 16 + gid;
            float b0v = bias ? bias[oc] : 0.f;
            float b1v = bias ? bias[oc + 8] : 0.f;
            float* r0p = out + ((size_t)b * OCT + oc) * HW + pl0 + wn * 16 + 2 * tig;
            float* r1p = r0p + (size_t)8 * HW;
#pragma unroll
            for (int nf = 0; nf < 2; nf++) {
                float2 v0 = {acc[mf][nf][0] + b0v, acc[mf][nf][1] + b0v};
                float2 v1 = {acc[mf][nf][2] + b1v, acc[mf][nf][3] + b1v};
                *(float2*)(r0p + nf * 8) = v0;
                *(float2*)(r1p + nf * 8) = v1;
            }
        }
    }
}

// ---------------- window attention: coalesced window-layout qkv, f32x2 math ----------------
// grid (576, NH/2, BATCH), block 128 (two 64-thread head groups)
__global__ void __launch_bounds__(128) attn_kernel(const float* __restrict__ rpb) {
    int win = blockIdx.x, b = blockIdx.z;
    int tid = threadIdx.x;
    int sub = tid >> 6, i = tid & 63;
    int hd = blockIdx.y * 2 + sub;

    __shared__ __align__(16) float qsm[2][1024];
    __shared__ __align__(16) float ksm[2][1024];
    __shared__ __align__(16) float vsm[2][1024];
    __shared__ float rsm[2][228];

    const float4* qb = (const float4*)(g_qkvw + qidx(0, b, hd, win));
    const float4* kb = (const float4*)(g_qkvw + qidx(1, b, hd, win));
    const float4* vb = (const float4*)(g_qkvw + qidx(2, b, hd, win));
    float4* qs4 = (float4*)qsm[sub];
    float4* ks4 = (float4*)ksm[sub];
    float4* vs4 = (float4*)vsm[sub];
#pragma unroll
    for (int t = 0; t < 4; t++) {
        qs4[i + t * 64] = qb[i + t * 64];
        ks4[i + t * 64] = kb[i + t * 64];
        vs4[i + t * 64] = vb[i + t * 64];
    }
#pragma unroll
    for (int t = i; t < 225; t += 64) rsm[sub][t] = rpb[t * 16 + hd];
    __syncthreads();

    int yi = i >> 3, xi = i & 7;
    const float* rs = rsm[sub] + (yi + 7) * 15 + (xi + 7);
    const float* ks = ksm[sub];
    const float* vs = vsm[sub];

    float2 q2[16];
#pragma unroll
    for (int d = 0; d < 16; d++) {
        float qd = qsm[sub][d * 64 + i];
        q2[d] = make_float2(qd, qd);
    }

    float2 lg2[32];
#pragma unroll
    for (int jj = 0; jj < 32; jj++) {
        float2 a = make_float2(0.f, 0.f);
#pragma unroll
        for (int d = 0; d < 16; d++)
            fma2(a, q2[d], *(const float2*)&ks[d * 64 + 2 * jj]);
        int j0 = 2 * jj, j1 = 2 * jj + 1;
        a.x = a.x * 0.25f + rs[-((j0 >> 3) * 15 + (j0 & 7))];
        a.y = a.y * 0.25f + rs[-((j1 >> 3) * 15 + (j1 & 7))];
        lg2[jj] = a;
    }
    float mx = -1e30f;
#pragma unroll
    for (int jj = 0; jj < 32; jj++) mx = fmaxf(mx, fmaxf(lg2[jj].x, lg2[jj].y));
    float s = 0.f;
#pragma unroll
    for (int jj = 0; jj < 32; jj++) {
        lg2[jj].x = __expf(lg2[jj].x - mx);
        lg2[jj].y = __expf(lg2[jj].y - mx);
        s += lg2[jj].x + lg2[jj].y;
    }
    float inv = 1.f / s;

    float2 a2[16];
#pragma unroll
    for (int d = 0; d < 16; d++) a2[d] = make_float2(0.f, 0.f);
#pragma unroll
    for (int jj = 0; jj < 32; jj++) {
        float2 p2 = lg2[jj];
#pragma unroll
        for (int d = 0; d < 16; d++)
            fma2(a2[d], p2, *(const float2*)&vs[d * 64 + 2 * jj]);
    }

    __syncthreads();   // done reading qsm everywhere before re-using it as staging
#pragma unroll
    for (int d = 0; d < 16; d++)
        qsm[sub][d * 64 + i] = (a2[d].x + a2[d].y) * inv;
    __syncthreads();

    // coalesced 32B stores into spatial layout g_attn[b][c][pix]
    int py0 = (win / 24) * 8, px0 = (win - (win / 24) * 24) * 8;
#pragma unroll
    for (int t = 0; t < 2; t++) {
        int R = tid * 2 + t;              // 0..255: [h2][d][row]
        int h2 = R >> 7, d = (R >> 3) & 15, r = R & 7;
        int c = (blockIdx.y * 2 + h2) * 16 + d;
        float* gp = g_attn + ((size_t)(b * 256 + c)) * HW + (size_t)(py0 + r) * 192 + px0;
        float4 v0 = *(float4*)&qsm[h2][d * 64 + r * 8];
        float4 v1 = *(float4*)&qsm[h2][d * 64 + r * 8 + 4];
        *(float4*)gp = v0;
        *(float4*)(gp + 4) = v1;
    }
}

// ---------------- stitch: ax + ay + local, 2 pixels/thread via float2 ----------------
__global__ void stitch_kernel() {
    size_t idx = (size_t)blockIdx.x * 256 + threadIdx.x;   // over BATCH*CC*HW/2
    int pw = (int)(idx % (HW / 2));
    size_t bc = idx / (HW / 2);
    int h = pw / 96, w2 = pw - (pw / 96) * 96;
    int w0 = 2 * w2;
    const float* plane = g_attn + bc * HW;
    const float2* plane2 = (const float2*)plane;

    // vertical 8-tap (float2 covers both pixels)
    float2 sx = make_float2(0.f, 0.f);
#pragma unroll
    for (int o = -3; o <= 4; o++) {
        int t = h + o;
        if (t >= 0 && t <= HH) {
            if (t == HH) t = HH - 2;
            add2(sx, plane2[t * 96 + w2]);
        }
    }

    // horizontal 8-tap for both pixels: need values w0-3..w0+5
    float hv[10];   // hv[j] = plane[h][w0-4+j]
    const float* row = plane + (size_t)h * 192;
    if (w0 >= 4 && w0 <= 186) {
#pragma unroll
        for (int q = 0; q < 5; q++) {
            float2 v = *(const float2*)(row + w0 - 4 + 2 * q);
            hv[2 * q] = v.x; hv[2 * q + 1] = v.y;
        }
    } else {
#pragma unroll
        for (int j = 0; j < 10; j++) {
            int u = w0 - 4 + j;
            float v = 0.f;
            if (u >= 0 && u <= WWID) {
                if (u == WWID) u = WWID - 2;
                v = row[u];
            }
            hv[j] = v;
        }
    }
    float2 sy;
    sy.x = hv[1] + hv[2] + hv[3] + hv[4] + hv[5] + hv[6] + hv[7] + hv[8];
    sy.y = hv[2] + hv[3] + hv[4] + hv[5] + hv[6] + hv[7] + hv[8] + hv[9];

    float2 loc = *(const float2*)(g_local + bc * HW + (size_t)h * 192 + w0);
    float2 o2;
    o2.x = (sx.x + sy.x) * 0.125f + loc.x;
    o2.y = (sx.y + sy.y) * 0.125f + loc.y;
    *(float2*)(g_st + bc * HW + (size_t)h * 192 + w0) = o2;
}

// ---------------- depthwise 8x8 conv: channel-pair f32x2, fused fp16 pack ----------------
// block: 16 channels (8 pairs) x (32x8) pixels; writes g_dwt2 [p][c] fp16 directly
__global__ void __launch_bounds__(256) dwconv_kernel(const float* __restrict__ w_dw) {
    __shared__ float2 patch[8][15][40];
    __shared__ float2 wsm[8][64];
    int cg = blockIdx.z & 15;            // channel group (16 channels)
    int b = blockIdx.z >> 4;
    int c0 = cg * 16;
    int ox0 = blockIdx.x * 32, oy0 = blockIdx.y * 8;
    int tid = threadIdx.x;

    for (int e = tid; e < 8 * 64; e += 256) {
        int cp = e >> 6, t = e & 63;
        wsm[cp][t] = make_float2(w_dw[(c0 + 2 * cp) * 64 + t],
                                 w_dw[(c0 + 2 * cp + 1) * 64 + t]);
    }
#pragma unroll 1
    for (int cp = 0; cp < 8; cp++) {
        const float* p0 = g_st + ((size_t)(b * CC + c0 + 2 * cp)) * HW;
        const float* p1 = p0 + HW;
        for (int e = tid; e < 15 * 39; e += 256) {
            int iy = e / 39, jx = e - iy * 39;
            int sy = oy0 - 3 + iy, sx = ox0 - 3 + jx;
            float2 v = make_float2(0.f, 0.f);
            if (sy >= 0 && sy <= HH && sx >= 0 && sx <= WWID) {   // padded 193x193
                int yy = (sy == HH) ? (HH - 2) : sy;
                int xx = (sx == WWID) ? (WWID - 2) : sx;
                v.x = p0[(size_t)yy * WWID + xx];
                v.y = p1[(size_t)yy * WWID + xx];
            }
            patch[cp][iy][jx] = v;
        }
    }
    __syncthreads();

    int tx = tid & 31, ty = tid >> 5;
    __half ob[16];
#pragma unroll 1
    for (int cp = 0; cp < 8; cp++) {
        float2 acc = make_float2(0.f, 0.f);
#pragma unroll
        for (int ky = 0; ky < 8; ky++)
#pragma unroll
            for (int kx = 0; kx < 8; kx++)
                fma2(acc, wsm[cp][ky * 8 + kx], patch[cp][ty + ky][tx + kx]);
        ob[2 * cp] = __float2half_rn(acc.x);
        ob[2 * cp + 1] = __float2half_rn(acc.y);
    }
    int p = (oy0 + ty) * WWID + ox0 + tx;
    __half* dst = g_dwt2 + ((size_t)b * HW + p) * 256 + c0;   // 32B contiguous
    *(uint4*)dst = *(uint4*)ob;
    *(uint4*)(dst + 8) = *(uint4*)(ob + 8);
}

// ---------------- launch: forked-stream DAG (graph-capturable fork/join) ----------------
extern "C" void kernel_launch(void* const* d_in, const int* in_sizes, int n_in,
                              void* d_out, int out_size) {
    const float* x        = (const float*)d_in[0];
    const float* w_qkv    = (const float*)d_in[1];
    const float* w_local1 = (const float*)d_in[2];
    const float* bn1_s    = (const float*)d_in[3];
    const float* bn1_b    = (const float*)d_in[4];
    const float* w_local2 = (const float*)d_in[5];
    const float* bn2_s    = (const float*)d_in[6];
    const float* bn2_b    = (const float*)d_in[7];
    const float* w_dw     = (const float*)d_in[8];
    const float* bnp_s    = (const float*)d_in[9];
    const float* bnp_b    = (const float*)d_in[10];
    const float* w_pw     = (const float*)d_in[11];
    const float* rpb      = (const float*)d_in[12];
    float* out = (float*)d_out;

    const int SMEM_GEMM = 3 * 24576;
    cudaFuncSetAttribute(gemm_kernel<0>, cudaFuncAttributeMaxDynamicSharedMemorySize, SMEM_GEMM);
    cudaFuncSetAttribute(gemm_kernel<1>, cudaFuncAttributeMaxDynamicSharedMemorySize, SMEM_GEMM);
    cudaFuncSetAttribute(gemm_kernel<2>, cudaFuncAttributeMaxDynamicSharedMemorySize, SMEM_GEMM);

    // ONE extra stream only (a second forked stream trips the harness's
    // post-teardown device-memory check).
    cudaStream_t s2;
    cudaStreamCreateWithFlags(&s2, cudaStreamNonBlocking);
    cudaEvent_t eStart, ePrep, eX, eAttn;
    cudaEventCreateWithFlags(&eStart, cudaEventDisableTiming);
    cudaEventCreateWithFlags(&ePrep, cudaEventDisableTiming);
    cudaEventCreateWithFlags(&eX, cudaEventDisableTiming);
    cudaEventCreateWithFlags(&eAttn, cudaEventDisableTiming);

    cudaEventRecord(eStart, 0);
    cudaStreamWaitEvent(s2, eStart, 0);

    // s2: weight fusion + packing
    fuse_weights<<<(CC * CC * 9 + 255) / 256, 256, 0, s2>>>(w_local1, bn1_s, bn1_b,
                                                            w_local2, bn2_s, bn2_b,
                                                            w_pw, bnp_s, bnp_b);
    prep_pack<<<(CC * 2304 + 255) / 256, 256, 0, s2>>>(w_qkv);
    cudaEventRecord(ePrep, s2);

    // main: activation transpose/convert (concurrent with prep)
    tconv_kernel<<<dim3(HW / 32, CC / 32, BATCH), dim3(32, 8)>>>(x);
    cudaEventRecord(eX, 0);

    // s2: qkv GEMM then attention
    cudaStreamWaitEvent(s2, eX, 0);
    gemm_kernel<0><<<dim3(6, PT2), 256, SMEM_GEMM, s2>>>(nullptr);
    attn_kernel<<<dim3(576, NH / 2, BATCH), 128, 0, s2>>>(rpb);
    cudaEventRecord(eAttn, s2);

    // main: conv3x3 GEMM concurrent with side
    cudaStreamWaitEvent(0, ePrep, 0);
    gemm_kernel<1><<<dim3(2, PT2), 256, SMEM_GEMM>>>(nullptr);

    // join: stitch needs g_attn (side) + g_local (main)
    cudaStreamWaitEvent(0, eAttn, 0);
    stitch_kernel<<<(unsigned)((size_t)BATCH * CC * HW / 512), 256>>>();
    dwconv_kernel<<<dim3(WWID / 32, HH / 8, BATCH * 16), 256>>>(w_dw);
    gemm_kernel<2><<<dim3(2, PT2), 256, SMEM_GEMM>>>(out);
}

// round 16
// speedup vs baseline: 1.0393x; 1.0393x over previous
#include <cuda_runtime.h>
#include <cuda_bf16.h>
#include <cuda_fp16.h>
#include <stdint.h>

#define BATCH 4
#define CC    256
#define HH    192
#define WWID  192
#define HW    (HH*WWID)
#define NH    16
#define DH    16
#define WS    8
#define PB    288          // 128-pixel tiles per batch image
#define PT    (PB*BATCH)   // 1152 total p-tiles

// ---------------- scratch (static device globals; no allocation) ----------------
// plain fp16 activations, [b][p][c] channel-contiguous
__device__ __align__(16) __half g_xt2[(size_t)BATCH * HW * CC];
__device__ __align__(16) __half g_dwt2[(size_t)BATCH * HW * CC];
__device__ __align__(16) float g_qkvw[(size_t)3 * BATCH * NH * 576 * DH * 64]; // window layout
__device__ float g_local[(size_t)BATCH * CC * HW];
__device__ float g_attn[(size_t)BATCH * CC * HW];
__device__ float g_st[(size_t)BATCH * CC * HW];
__device__ float g_wl[CC * CC * 9];
__device__ float g_bl[CC];
__device__ float g_wpw[CC * CC];
__device__ float g_bpw[CC];
__device__ __align__(16) __half g_wqA[768 * CC];      // [oc][k] fp16
__device__ __align__(16) __half g_wlA[CC * 9 * CC];   // [oc][t*256+ic] fp16
__device__ __align__(16) __half g_wpA[CC * CC];       // [oc][k] fp16

// ---------------- PTX helpers (baseline sm_80+/sm_100 features only) ----------------
__device__ __forceinline__ uint32_t s2u(const void* p) {
    uint32_t a;
    asm("{ .reg .u64 t; cvta.to.shared.u64 t, %1; cvt.u32.u64 %0, t; }" : "=r"(a) : "l"(p));
    return a;
}
__device__ __forceinline__ void cp16(uint32_t s, const void* g) {
    asm volatile("cp.async.cg.shared.global [%0], [%1], 16;" :: "r"(s), "l"(g));
}
__device__ __forceinline__ void cp16z(uint32_t s, const void* g, int sz) {
    asm volatile("cp.async.cg.shared.global [%0], [%1], 16, %2;" :: "r"(s), "l"(g), "r"(sz));
}
#define CP_COMMIT() asm volatile("cp.async.commit_group;" ::: "memory")
#define CP_WAIT(N)  asm volatile("cp.async.wait_group %0;" :: "n"(N) : "memory")

#define LDSM4(r, addr) \
    asm volatile("ldmatrix.sync.aligned.m8n8.x4.shared.b16 {%0,%1,%2,%3}, [%4];" \
        : "=r"((r)[0]), "=r"((r)[1]), "=r"((r)[2]), "=r"((r)[3]) : "r"(addr))

// fp16 inputs, fp32 accumulate
#define MMA16816(d, a, b0v, b1v) \
    asm volatile("mma.sync.aligned.m16n8k16.row.col.f32.f16.f16.f32 " \
        "{%0,%1,%2,%3},{%4,%5,%6,%7},{%8,%9},{%0,%1,%2,%3};" \
        : "+f"((d)[0]), "+f"((d)[1]), "+f"((d)[2]), "+f"((d)[3]) \
        : "r"((a)[0]), "r"((a)[1]), "r"((a)[2]), "r"((a)[3]), "r"(b0v), "r"(b1v))

// packed dual-fp32 FMA (Blackwell): d = a*b + d
__device__ __forceinline__ void fma2(float2& d, const float2& a, const float2& b) {
    asm("fma.rn.f32x2 %0, %1, %2, %0;"
        : "+l"(reinterpret_cast<unsigned long long&>(d))
        : "l"(reinterpret_cast<const unsigned long long&>(a)),
          "l"(reinterpret_cast<const unsigned long long&>(b)));
}
__device__ __forceinline__ void add2(float2& d, const float2& a) {
    asm("add.rn.f32x2 %0, %1, %0;"
        : "+l"(reinterpret_cast<unsigned long long&>(d))
        : "l"(reinterpret_cast<const unsigned long long&>(a)));
}

__device__ __host__ __forceinline__ size_t qidx(int sel, int b, int hd, int win) {
    return ((size_t)((sel * 4 + b) * 16 + hd) * 576 + win) * 1024;
}

// ---------------- weight fusion (fp32) ----------------
__global__ void fuse_weights(const float* __restrict__ w_local1,
                             const float* __restrict__ bn1_s, const float* __restrict__ bn1_b,
                             const float* __restrict__ w_local2,
                             const float* __restrict__ bn2_s, const float* __restrict__ bn2_b,
                             const float* __restrict__ w_pw,
                             const float* __restrict__ bnp_s, const float* __restrict__ bnp_b) {
    int i = blockIdx.x * blockDim.x + threadIdx.x;
    const int N1 = CC * CC * 9;
    if (i < N1) {
        int oc = i / (CC * 9);
        int r = i - oc * (CC * 9);
        int ic = r / 9;
        int t = r - ic * 9;
        float v = bn1_s[oc] * w_local1[i];
        if (t == 4) v += bn2_s[oc] * w_local2[oc * CC + ic];
        g_wl[i] = v;
    }
    if (i < CC * CC) {
        int ic = i & (CC - 1);
        g_wpw[i] = w_pw[i] * bnp_s[ic];
    }
    if (i < CC) {
        g_bl[i] = bn1_b[i] + bn2_b[i];
        float s = 0.f;
        for (int ic = 0; ic < CC; ic++) s += w_pw[i * CC + ic] * bnp_b[ic];
        g_bpw[i] = s;
    }
}

// ---------------- weight fp16 packing ----------------
__global__ void prep_pack(const float* __restrict__ w_qkv) {
    int i = blockIdx.x * blockDim.x + threadIdx.x;
    if (i < 768 * 256) g_wqA[i] = __float2half_rn(w_qkv[i]);
    if (i < 256 * 256) g_wpA[i] = __float2half_rn(g_wpw[i]);
    if (i < 256 * 2304) {   // k = t*256+ic maps from g_wl[oc][ic*9+t]
        int oc = i / 2304;
        int k = i - oc * 2304;
        int t = k >> 8, ic = k & 255;
        g_wlA[i] = __float2half_rn(g_wl[oc * 2304 + ic * 9 + t]);
    }
}

// ---------------- transpose + convert: x [b][c][p] fp32 -> [b][p][c] fp16 ----------------
__global__ void tconv_kernel(const float* __restrict__ xin) {
    __shared__ float t[32][33];
    int b = blockIdx.z, c0 = blockIdx.y * 32, p0 = blockIdx.x * 32;
    int tx = threadIdx.x, ty = threadIdx.y;
#pragma unroll
    for (int i = 0; i < 4; i++)
        t[ty + i * 8][tx] = xin[((size_t)(b * CC + c0 + ty + i * 8)) * HW + p0 + tx];
    __syncthreads();
#pragma unroll
    for (int i = 0; i < 4; i++) {
        int p = p0 + ty + i * 8;
        g_xt2[((size_t)b * HW + p) * CC + c0 + tx] = __float2half_rn(t[tx][ty + i * 8]);
    }
}

// ---------------- mma.sync plain-fp16 GEMM (fp32 accumulate), 128x128 tile ----------------
// D[oc][p] = sum_k W[oc][k] * X[p][k]
// grid = (oc_tiles, pixel_tiles); b = bBase + ti/PB
// OP: 0 = qkv (OC=768) -> window layout g_qkvw
//     1 = conv3x3 implicit (OC=256, K=2304 t-outer) -> g_local
//     2 = pointwise (OC=256) -> outp
template<int OP>
__global__ void __launch_bounds__(256, 2) gemm_kernel(float* __restrict__ outp, int bBase) {
    extern __shared__ char smem[];
    const int NCH = (OP == 1) ? 36 : 4;   // chunks of 64 real k
    const int OCT = (OP == 0) ? 768 : 256;
    const uint4* A = (OP == 0) ? (const uint4*)g_wqA : (OP == 1) ? (const uint4*)g_wlA : (const uint4*)g_wpA;
    const uint4* X = (OP == 2) ? (const uint4*)g_dwt2 : (const uint4*)g_xt2;
    const float* bias = (OP == 1) ? g_bl : (OP == 2) ? g_bpw : nullptr;
    float* out = (OP == 1) ? g_local : outp;
    const int AR = NCH * 8;               // uint4 per A row
    const int XR = 32;                    // uint4 per X pixel row (256 fp16)

    uint32_t sb = s2u(smem);
    int tid = threadIdx.x;
    int ti = blockIdx.y;                  // pixel tile (slow)
    int b = bBase + ti / PB;
    int pl0 = (ti - (ti / PB) * PB) * 128;
    int oc0 = blockIdx.x * 128;           // oc tile (fast) -> wave shares B in L2

    // ---- per-thread loader constants (i-invariant: c16 and row&7 fixed) ----
    int r0 = tid >> 3, c16 = tid & 7;
    uint32_t swz = (uint32_t)((c16 ^ (r0 & 7)) << 4);
    uint32_t sArel = (uint32_t)(r0 * 128) + swz;            // + i*4096
    const uint4* aCur = A + (size_t)(oc0 + r0) * AR + c16;  // += 8 per chunk
    const uint4* xCur;                                       // OP!=1
    const uint4* xPtr[4];                                    // OP==1
    int hI[4], wI[4];
    if (OP != 1) {
        xCur = X + ((size_t)b * HW + pl0 + r0) * XR + c16;
    } else {
#pragma unroll
        for (int i = 0; i < 4; i++) {
            int pl = pl0 + r0 + 32 * i;
            hI[i] = pl / 192; wI[i] = pl - hI[i] * 192;
            xPtr[i] = X + ((size_t)b * HW + pl) * XR + c16;
        }
    }

    auto load_chunk = [&](int c, uint32_t Ab) {
#pragma unroll
        for (int i = 0; i < 4; i++)
            cp16(Ab + sArel + i * 4096, aCur + (size_t)i * 32 * AR);
        aCur += 8;
        if (OP != 1) {
#pragma unroll
            for (int i = 0; i < 4; i++)
                cp16(Ab + 16384 + sArel + i * 4096, xCur + i * 32 * XR);
            xCur += 8;
        } else {
            int t = c >> 2, cc = c & 3;                      // 4 chunks per tap
            int ky = t / 3 - 1, kx = t - (t / 3) * 3 - 1;
            int off = (ky * 192 + kx) * XR + cc * 8;         // uniform scalar
#pragma unroll
            for (int i = 0; i < 4; i++) {
                bool ok = ((unsigned)(hI[i] + ky) < 192u) && ((unsigned)(wI[i] + kx) < 192u);
                cp16z(Ab + 16384 + sArel + i * 4096, ok ? (xPtr[i] + off) : X, ok ? 16 : 0);
            }
        }
        CP_COMMIT();
    };

    float acc[4][4][4];
#pragma unroll
    for (int mf = 0; mf < 4; mf++)
#pragma unroll
        for (int nf = 0; nf < 4; nf++)
#pragma unroll
            for (int e = 0; e < 4; e++) acc[mf][nf][e] = 0.f;

    int lane = tid & 31, w = tid >> 5, wm = w & 1, wn = w >> 1;
    int la = lane & 15, ls = lane >> 4;
    int sAsw = la & 7;
    int brow_i = wn * 32 + (lane & 7) + ((lane >> 3) & 1) * 8;
    int sBsw = lane & 7;
    uint32_t arowRel = (uint32_t)((wm * 64 + la) * 128);
    uint32_t browRel = 16384u + (uint32_t)(brow_i * 128);
    uint32_t achK[4], bchK[4];
#pragma unroll
    for (int kp = 0; kp < 4; kp++) {
        achK[kp] = (uint32_t)(((2 * kp + ls) ^ sAsw) << 4);
        bchK[kp] = (uint32_t)(((2 * kp + ls) ^ sBsw) << 4);
    }

    load_chunk(0, sb);
    load_chunk(1, sb + 32768);
    uint32_t AbC = sb;                 // compute buffer
    uint32_t AbL = sb + 65536;         // next load buffer
    for (int c = 0; c < NCH; c++) {
        if (c == NCH - 1) { CP_WAIT(0); } else { CP_WAIT(1); }
        __syncthreads();
        if (c + 2 < NCH) {
            load_chunk(c + 2, AbL);
            AbL += 32768; if (AbL == sb + 98304) AbL = sb;
        }
        uint32_t arow = AbC + arowRel;
        uint32_t brow = AbC + browRel;
        AbC += 32768; if (AbC == sb + 98304) AbC = sb;
#pragma unroll
        for (int kp = 0; kp < 4; kp++) {
            uint32_t brh[2][4];
            LDSM4(brh[0], brow + bchK[kp]); LDSM4(brh[1], brow + 2048 + bchK[kp]);
#pragma unroll
            for (int mf = 0; mf < 4; mf++) {
                uint32_t ah[4];
                LDSM4(ah, arow + mf * 2048 + achK[kp]);
#pragma unroll
                for (int nf = 0; nf < 4; nf++)
                    MMA16816(acc[mf][nf], ah, brh[nf >> 1][nf & 1], brh[nf >> 1][(nf & 1) + 2]);
            }
        }
    }

    // epilogue
    int gid = lane >> 2, tig = lane & 3;
    if (OP == 0) {
        // scatter into window layout [sel][b][hd][win][d][token]
#pragma unroll
        for (int mf = 0; mf < 4; mf++) {
#pragma unroll
            for (int r = 0; r < 2; r++) {
                int ocr = oc0 + wm * 64 + mf * 16 + gid + r * 8;
                int sel = ocr >> 8, hd = (ocr >> 4) & 15, d = ocr & 15;
                float* bp = g_qkvw + qidx(sel, b, hd, 0) + d * 64;
#pragma unroll
                for (int nf = 0; nf < 4; nf++) {
                    int pixel = pl0 + wn * 32 + 2 * tig + nf * 8;
                    int py = pixel / 192, px = pixel - py * 192;
                    int win = (py >> 3) * 24 + (px >> 3);
                    int token = ((py & 7) << 3) + (px & 7);
                    float2 v = {acc[mf][nf][2 * r], acc[mf][nf][2 * r + 1]};
                    *(float2*)(bp + (size_t)win * 1024 + token) = v;
                }
            }
        }
    } else {
#pragma unroll
        for (int mf = 0; mf < 4; mf++) {
            int oc = oc0 + wm * 64 + mf * 16 + gid;
            float b0v = bias ? bias[oc] : 0.f;
            float b1v = bias ? bias[oc + 8] : 0.f;
            float* r0p = out + ((size_t)b * OCT + oc) * HW + pl0 + wn * 32 + 2 * tig;
            float* r1p = r0p + (size_t)8 * HW;
#pragma unroll
            for (int nf = 0; nf < 4; nf++) {
                float2 v0 = {acc[mf][nf][0] + b0v, acc[mf][nf][1] + b0v};
                float2 v1 = {acc[mf][nf][2] + b1v, acc[mf][nf][3] + b1v};
                *(float2*)(r0p + nf * 8) = v0;
                *(float2*)(r1p + nf * 8) = v1;
            }
        }
    }
}

// ---------------- window attention: coalesced window-layout qkv, f32x2 math ----------------
// grid (576, NH/2, BATCH), block 128 (two 64-thread head groups)
__global__ void __launch_bounds__(128) attn_kernel(const float* __restrict__ rpb) {
    int win = blockIdx.x, b = blockIdx.z;
    int tid = threadIdx.x;
    int sub = tid >> 6, i = tid & 63;
    int hd = blockIdx.y * 2 + sub;

    __shared__ __align__(16) float qsm[2][1024];
    __shared__ __align__(16) float ksm[2][1024];
    __shared__ __align__(16) float vsm[2][1024];
    __shared__ float rsm[2][228];

    const float4* qb = (const float4*)(g_qkvw + qidx(0, b, hd, win));
    const float4* kb = (const float4*)(g_qkvw + qidx(1, b, hd, win));
    const float4* vb = (const float4*)(g_qkvw + qidx(2, b, hd, win));
    float4* qs4 = (float4*)qsm[sub];
    float4* ks4 = (float4*)ksm[sub];
    float4* vs4 = (float4*)vsm[sub];
#pragma unroll
    for (int t = 0; t < 4; t++) {
        qs4[i + t * 64] = qb[i + t * 64];
        ks4[i + t * 64] = kb[i + t * 64];
        vs4[i + t * 64] = vb[i + t * 64];
    }
#pragma unroll
    for (int t = i; t < 225; t += 64) rsm[sub][t] = rpb[t * 16 + hd];
    __syncthreads();

    int yi = i >> 3, xi = i & 7;
    const float* rs = rsm[sub] + (yi + 7) * 15 + (xi + 7);
    const float* ks = ksm[sub];
    const float* vs = vsm[sub];

    float2 q2[16];
#pragma unroll
    for (int d = 0; d < 16; d++) {
        float qd = qsm[sub][d * 64 + i];
        q2[d] = make_float2(qd, qd);
    }

    float2 lg2[32];
#pragma unroll
    for (int jj = 0; jj < 32; jj++) {
        float2 a = make_float2(0.f, 0.f);
#pragma unroll
        for (int d = 0; d < 16; d++)
            fma2(a, q2[d], *(const float2*)&ks[d * 64 + 2 * jj]);
        int j0 = 2 * jj, j1 = 2 * jj + 1;
        a.x = a.x * 0.25f + rs[-((j0 >> 3) * 15 + (j0 & 7))];
        a.y = a.y * 0.25f + rs[-((j1 >> 3) * 15 + (j1 & 7))];
        lg2[jj] = a;
    }
    float mx = -1e30f;
#pragma unroll
    for (int jj = 0; jj < 32; jj++) mx = fmaxf(mx, fmaxf(lg2[jj].x, lg2[jj].y));
    float s = 0.f;
#pragma unroll
    for (int jj = 0; jj < 32; jj++) {
        lg2[jj].x = __expf(lg2[jj].x - mx);
        lg2[jj].y = __expf(lg2[jj].y - mx);
        s += lg2[jj].x + lg2[jj].y;
    }
    float inv = 1.f / s;

    float2 a2[16];
#pragma unroll
    for (int d = 0; d < 16; d++) a2[d] = make_float2(0.f, 0.f);
#pragma unroll
    for (int jj = 0; jj < 32; jj++) {
        float2 p2 = lg2[jj];
#pragma unroll
        for (int d = 0; d < 16; d++)
            fma2(a2[d], p2, *(const float2*)&vs[d * 64 + 2 * jj]);
    }

    __syncthreads();   // done reading qsm everywhere before re-using it as staging
#pragma unroll
    for (int d = 0; d < 16; d++)
        qsm[sub][d * 64 + i] = (a2[d].x + a2[d].y) * inv;
    __syncthreads();

    // coalesced 32B stores into spatial layout g_attn[b][c][pix]
    int py0 = (win / 24) * 8, px0 = (win - (win / 24) * 24) * 8;
#pragma unroll
    for (int t = 0; t < 2; t++) {
        int R = tid * 2 + t;              // 0..255: [h2][d][row]
        int h2 = R >> 7, d = (R >> 3) & 15, r = R & 7;
        int c = (blockIdx.y * 2 + h2) * 16 + d;
        float* gp = g_attn + ((size_t)(b * 256 + c)) * HW + (size_t)(py0 + r) * 192 + px0;
        float4 v0 = *(float4*)&qsm[h2][d * 64 + r * 8];
        float4 v1 = *(float4*)&qsm[h2][d * 64 + r * 8 + 4];
        *(float4*)gp = v0;
        *(float4*)(gp + 4) = v1;
    }
}

// ---------------- stitch: ax + ay + local, 2 pixels/thread, 2 batches per launch ----------------
__global__ void stitch_kernel(int b0) {
    size_t idx = (size_t)blockIdx.x * 256 + threadIdx.x;   // over 2*CC*HW/2
    int pw = (int)(idx % (HW / 2));
    size_t bc = (size_t)b0 * CC + idx / (HW / 2);
    int h = pw / 96, w2 = pw - (pw / 96) * 96;
    int w0 = 2 * w2;
    const float* plane = g_attn + bc * HW;
    const float2* plane2 = (const float2*)plane;

    float2 sx = make_float2(0.f, 0.f);
#pragma unroll
    for (int o = -3; o <= 4; o++) {
        int t = h + o;
        if (t >= 0 && t <= HH) {
            if (t == HH) t = HH - 2;
            add2(sx, plane2[t * 96 + w2]);
        }
    }

    float hv[10];   // hv[j] = plane[h][w0-4+j]
    const float* row = plane + (size_t)h * 192;
    if (w0 >= 4 && w0 <= 186) {
#pragma unroll
        for (int q = 0; q < 5; q++) {
            float2 v = *(const float2*)(row + w0 - 4 + 2 * q);
            hv[2 * q] = v.x; hv[2 * q + 1] = v.y;
        }
    } else {
#pragma unroll
        for (int j = 0; j < 10; j++) {
            int u = w0 - 4 + j;
            float v = 0.f;
            if (u >= 0 && u <= WWID) {
                if (u == WWID) u = WWID - 2;
                v = row[u];
            }
            hv[j] = v;
        }
    }
    float2 sy;
    sy.x = hv[1] + hv[2] + hv[3] + hv[4] + hv[5] + hv[6] + hv[7] + hv[8];
    sy.y = hv[2] + hv[3] + hv[4] + hv[5] + hv[6] + hv[7] + hv[8] + hv[9];

    float2 loc = *(const float2*)(g_local + bc * HW + (size_t)h * 192 + w0);
    float2 o2;
    o2.x = (sx.x + sy.x) * 0.125f + loc.x;
    o2.y = (sx.y + sy.y) * 0.125f + loc.y;
    *(float2*)(g_st + bc * HW + (size_t)h * 192 + w0) = o2;
}

// ---------------- depthwise 8x8 conv: channel-pair f32x2, 2 batches per launch ----------------
__global__ void __launch_bounds__(256) dwconv_kernel(const float* __restrict__ w_dw, int b0) {
    __shared__ float2 patch[8][15][40];
    __shared__ float2 wsm[8][64];
    int cg = blockIdx.z & 15;            // channel group (16 channels)
    int b = b0 + (blockIdx.z >> 4);
    int c0 = cg * 16;
    int ox0 = blockIdx.x * 32, oy0 = blockIdx.y * 8;
    int tid = threadIdx.x;

    for (int e = tid; e < 8 * 64; e += 256) {
        int cp = e >> 6, t = e & 63;
        wsm[cp][t] = make_float2(w_dw[(c0 + 2 * cp) * 64 + t],
                                 w_dw[(c0 + 2 * cp + 1) * 64 + t]);
    }
#pragma unroll 1
    for (int cp = 0; cp < 8; cp++) {
        const float* p0 = g_st + ((size_t)(b * CC + c0 + 2 * cp)) * HW;
        const float* p1 = p0 + HW;
        for (int e = tid; e < 15 * 39; e += 256) {
            int iy = e / 39, jx = e - iy * 39;
            int sy = oy0 - 3 + iy, sx = ox0 - 3 + jx;
            float2 v = make_float2(0.f, 0.f);
            if (sy >= 0 && sy <= HH && sx >= 0 && sx <= WWID) {   // padded 193x193
                int yy = (sy == HH) ? (HH - 2) : sy;
                int xx = (sx == WWID) ? (WWID - 2) : sx;
                v.x = p0[(size_t)yy * WWID + xx];
                v.y = p1[(size_t)yy * WWID + xx];
            }
            patch[cp][iy][jx] = v;
        }
    }
    __syncthreads();

    int tx = tid & 31, ty = tid >> 5;
    __half ob[16];
#pragma unroll 1
    for (int cp = 0; cp < 8; cp++) {
        float2 acc = make_float2(0.f, 0.f);
#pragma unroll
        for (int ky = 0; ky < 8; ky++)
#pragma unroll
            for (int kx = 0; kx < 8; kx++)
                fma2(acc, wsm[cp][ky * 8 + kx], patch[cp][ty + ky][tx + kx]);
        ob[2 * cp] = __float2half_rn(acc.x);
        ob[2 * cp + 1] = __float2half_rn(acc.y);
    }
    int p = (oy0 + ty) * WWID + ox0 + tx;
    __half* dst = g_dwt2 + ((size_t)b * HW + p) * 256 + c0;   // 32B contiguous
    *(uint4*)dst = *(uint4*)ob;
    *(uint4*)(dst + 8) = *(uint4*)(ob + 8);
}

// ---------------- launch: fork/join DAG, tail split by batch halves ----------------
extern "C" void kernel_launch(void* const* d_in, const int* in_sizes, int n_in,
                              void* d_out, int out_size) {
    const float* x        = (const float*)d_in[0];
    const float* w_qkv    = (const float*)d_in[1];
    const float* w_local1 = (const float*)d_in[2];
    const float* bn1_s    = (const float*)d_in[3];
    const float* bn1_b    = (const float*)d_in[4];
    const float* w_local2 = (const float*)d_in[5];
    const float* bn2_s    = (const float*)d_in[6];
    const float* bn2_b    = (const float*)d_in[7];
    const float* w_dw     = (const float*)d_in[8];
    const float* bnp_s    = (const float*)d_in[9];
    const float* bnp_b    = (const float*)d_in[10];
    const float* w_pw     = (const float*)d_in[11];
    const float* rpb      = (const float*)d_in[12];
    float* out = (float*)d_out;

    const int SMEM_GEMM = 3 * 32768;
    cudaFuncSetAttribute(gemm_kernel<0>, cudaFuncAttributeMaxDynamicSharedMemorySize, SMEM_GEMM);
    cudaFuncSetAttribute(gemm_kernel<1>, cudaFuncAttributeMaxDynamicSharedMemorySize, SMEM_GEMM);
    cudaFuncSetAttribute(gemm_kernel<2>, cudaFuncAttributeMaxDynamicSharedMemorySize, SMEM_GEMM);

    // ONE extra stream only (a second forked stream trips the harness's
    // post-teardown device-memory check).
    cudaStream_t s2;
    cudaStreamCreateWithFlags(&s2, cudaStreamNonBlocking);
    cudaEvent_t eStart, ePrep, eX, eAttn, eG1, eTail;
    cudaEventCreateWithFlags(&eStart, cudaEventDisableTiming);
    cudaEventCreateWithFlags(&ePrep, cudaEventDisableTiming);
    cudaEventCreateWithFlags(&eX, cudaEventDisableTiming);
    cudaEventCreateWithFlags(&eAttn, cudaEventDisableTiming);
    cudaEventCreateWithFlags(&eG1, cudaEventDisableTiming);
    cudaEventCreateWithFlags(&eTail, cudaEventDisableTiming);

    cudaEventRecord(eStart, 0);
    cudaStreamWaitEvent(s2, eStart, 0);

    // s2: weight fusion + packing
    fuse_weights<<<(CC * CC * 9 + 255) / 256, 256, 0, s2>>>(w_local1, bn1_s, bn1_b,
                                                            w_local2, bn2_s, bn2_b,
                                                            w_pw, bnp_s, bnp_b);
    prep_pack<<<(CC * 2304 + 255) / 256, 256, 0, s2>>>(w_qkv);
    cudaEventRecord(ePrep, s2);

    // main: activation transpose/convert (concurrent with prep)
    tconv_kernel<<<dim3(HW / 32, CC / 32, BATCH), dim3(32, 8)>>>(x);
    cudaEventRecord(eX, 0);

    // s2: qkv GEMM then attention
    cudaStreamWaitEvent(s2, eX, 0);
    gemm_kernel<0><<<dim3(6, PT), 256, SMEM_GEMM, s2>>>(nullptr, 0);
    attn_kernel<<<dim3(576, NH / 2, BATCH), 128, 0, s2>>>(rpb);
    cudaEventRecord(eAttn, s2);

    // main: conv3x3 GEMM concurrent with side
    cudaStreamWaitEvent(0, ePrep, 0);
    gemm_kernel<1><<<dim3(2, PT), 256, SMEM_GEMM>>>(nullptr, 0);
    cudaEventRecord(eG1, 0);

    // tail split by batch halves across the two streams:
    // main handles b=0..1 (after attn), s2 handles b=2..3 (after gemm1)
    cudaStreamWaitEvent(0, eAttn, 0);
    stitch_kernel<<<(unsigned)((size_t)2 * CC * HW / 512), 256>>>(0);
    dwconv_kernel<<<dim3(WWID / 32, HH / 8, 32), 256>>>(w_dw, 0);
    gemm_kernel<2><<<dim3(2, 2 * PB), 256, SMEM_GEMM>>>(out, 0);

    cudaStreamWaitEvent(s2, eG1, 0);
    stitch_kernel<<<(unsigned)((size_t)2 * CC * HW / 512), 256, 0, s2>>>(2);
    dwconv_kernel<<<dim3(WWID / 32, HH / 8, 32), 256, 0, s2>>>(w_dw, 2);
    gemm_kernel<2><<<dim3(2, 2 * PB), 256, SMEM_GEMM, s2>>>(out, 2);
    cudaEventRecord(eTail, s2);
    cudaStreamWaitEvent(0, eTail, 0);
}